// round 17
// baseline (speedup 1.0000x reference)
#include <cuda_runtime.h>
#include <cuda_fp16.h>
#include <cstdint>

#define BB 64
#define NN 512
#define CC 1024
#define KC 64
#define NCH (CC/KC)          // 16 k-chunks

// Scratch (allocation-free rule: __device__ globals)
__device__ float g_S[(size_t)BB * NN * NN];      // 67 MB gram matrices
__device__ unsigned int g_done[BB];              // per-batch tile arrival (+10/launch)

// smem: 4 planes per buffer (A1,A2,B1,B2), 128 rows x 64 halves,
// padded row stride 144 B for conflict-free ldmatrix.
#define ROWB   144
#define TILE_B (128 * ROWB)          // 18432
#define BUF_B  (4 * TILE_B)          // 73728
#define SMEM_TOTAL (2 * BUF_B)       // 147456 (epilogue reuses: masks 32KB + rdeg 2KB)

#define NTHR 384                     // 8 MMA warps + 4 producer warps

// named barriers: FULL0=1, FULL1=2, EMPTY0=3, EMPTY1=4
#define BAR_SYNC(id)   asm volatile("bar.sync %0, %1;"   :: "r"(id), "n"(NTHR) : "memory")
#define BAR_ARRIVE(id) asm volatile("bar.arrive %0, %1;" :: "r"(id), "n"(NTHR) : "memory")

__device__ __forceinline__ uint32_t smem_u32(const void* p) {
    uint32_t a;
    asm("{ .reg .u64 t; cvta.to.shared.u64 t, %1; cvt.u32.u64 %0, t; }"
        : "=r"(a) : "l"(p));
    return a;
}
__device__ __forceinline__ void ldsm4(uint32_t& r0, uint32_t& r1,
                                      uint32_t& r2, uint32_t& r3, uint32_t a) {
    asm volatile("ldmatrix.sync.aligned.m8n8.x4.shared.b16 {%0,%1,%2,%3}, [%4];"
                 : "=r"(r0), "=r"(r1), "=r"(r2), "=r"(r3) : "r"(a));
}
__device__ __forceinline__ void mma16816(float* d, const uint32_t* a,
                                         uint32_t b0, uint32_t b1) {
    asm volatile(
        "mma.sync.aligned.m16n8k16.row.col.f32.f16.f16.f32 "
        "{%0,%1,%2,%3}, {%4,%5,%6,%7}, {%8,%9}, {%0,%1,%2,%3};"
        : "+f"(d[0]), "+f"(d[1]), "+f"(d[2]), "+f"(d[3])
        : "r"(a[0]), "r"(a[1]), "r"(a[2]), "r"(a[3]), "r"(b0), "r"(b1));
}

// ---------------------------------------------------------------------------
// Fused kernel: warp-specialized HMMA split-fp16 GEMM (R6/R13 config =
// legacy-HMMA rate ceiling) + per-batch fused topk/normalize tail epilogue.
// The LAST CTA to finish a batch's 10 tiles (monotonic counter, +10/launch)
// runs that batch's top-32 threshold (prefix-skip radix w/ early-exit) and
// writes the normalized adjacency directly -- overlapped under remaining
// GEMM work of other batches.
// ---------------------------------------------------------------------------
__global__ __launch_bounds__(NTHR, 1)
void gemm_fused_kernel(const float* __restrict__ X, float* __restrict__ out)
{
    extern __shared__ __align__(16) char smem[];
    const unsigned char ITm[10] = {0,0,0,0,1,1,1,2,2,3};
    const unsigned char JTm[10] = {0,1,2,3,1,2,3,2,3,3};
    const int it = ITm[blockIdx.x];
    const int jt = JTm[blockIdx.x];
    const int b  = blockIdx.y;
    const int rbase = it * 128;
    const int cbase = jt * 128;

    const int tid  = threadIdx.x;
    const int wid  = tid >> 5;
    const int lane = tid & 31;
    const uint32_t sb = smem_u32(smem);
    const float* __restrict__ Xb = X + (size_t)b * NN * CC;

    float acc[4][4][4];
    #pragma unroll
    for (int f = 0; f < 4; f++)
        #pragma unroll
        for (int n = 0; n < 4; n++)
            #pragma unroll
            for (int q = 0; q < 4; q++) acc[f][n][q] = 0.0f;

    if (wid >= 8) {
        // ---------------- producer warps ----------------
        const int ptid = tid - 256;          // 0..127
        #pragma unroll 1
        for (int c = 0; c < NCH; c++) {
            const int bs = c & 1;
            if (c >= 2) BAR_SYNC(3 + bs);    // wait EMPTY[bs]
            char* base = smem + bs * BUF_B;
            const int k0 = c * KC;
            #pragma unroll
            for (int i = 0; i < 32; i++) {
                int u  = i * 128 + ptid;     // 0..4095 16B-units
                int t  = u >> 11;            // 0=A rows, 1=B rows
                int r  = (u >> 4) & 127;
                int f4 = u & 15;
                int grow = (t ? cbase : rbase) + r;
                float4 v = *(const float4*)(Xb + (size_t)grow * CC + k0 + f4 * 4);
                __half2 a1 = __floats2half2_rn(v.x, v.y);
                __half2 b1 = __floats2half2_rn(v.z, v.w);
                float2 fa = __half22float2(a1);
                float2 fb = __half22float2(b1);
                __half2 a2 = __floats2half2_rn(v.x - fa.x, v.y - fa.y);
                __half2 b2 = __floats2half2_rn(v.z - fb.x, v.w - fb.y);
                int off = r * ROWB + f4 * 8;
                *(uint2*)(base + (t*2+0) * TILE_B + off) =
                    make_uint2(*(uint32_t*)&a1, *(uint32_t*)&b1);
                *(uint2*)(base + (t*2+1) * TILE_B + off) =
                    make_uint2(*(uint32_t*)&a2, *(uint32_t*)&b2);
            }
            BAR_ARRIVE(1 + bs);              // signal FULL[bs]
        }
    } else {
        // ---------------- MMA consumer warps ----------------
        const int wm = wid >> 2;             // 0..1  -> 64-row slab
        const int wn = wid & 3;              // 0..3  -> 32-col slab
        const int lrow = lane & 15;
        const int lcol = (lane >> 4) * 16;

        #pragma unroll 1
        for (int c = 0; c < NCH; c++) {
            const int bs = c & 1;
            BAR_SYNC(1 + bs);                // wait FULL[bs]

            const uint32_t tb  = sb + bs * BUF_B;
            const uint32_t pA1 = tb;
            const uint32_t pA2 = tb + TILE_B;
            const uint32_t pB1 = tb + 2 * TILE_B;
            const uint32_t pB2 = tb + 3 * TILE_B;

            #pragma unroll
            for (int ks = 0; ks < 4; ks++) {
                const int kb = ks * 32;      // 16 halves = 32 B
                uint32_t a1[4][4], a2[4][4], b1r[2][4], b2r[2][4];
                #pragma unroll
                for (int f = 0; f < 4; f++) {
                    uint32_t ad = (wm * 64 + f * 16 + lrow) * ROWB + lcol + kb;
                    ldsm4(a1[f][0], a1[f][1], a1[f][2], a1[f][3], pA1 + ad);
                    ldsm4(a2[f][0], a2[f][1], a2[f][2], a2[f][3], pA2 + ad);
                }
                #pragma unroll
                for (int g = 0; g < 2; g++) {
                    uint32_t ad = (wn * 32 + g * 16 + lrow) * ROWB + lcol + kb;
                    ldsm4(b1r[g][0], b1r[g][1], b1r[g][2], b1r[g][3], pB1 + ad);
                    ldsm4(b2r[g][0], b2r[g][1], b2r[g][2], b2r[g][3], pB2 + ad);
                }
                #pragma unroll
                for (int f = 0; f < 4; f++)
                    #pragma unroll
                    for (int g = 0; g < 2; g++)
                        #pragma unroll
                        for (int h = 0; h < 2; h++) {
                            float* d = acc[f][g*2+h];
                            mma16816(d, a1[f], b1r[g][0+h], b1r[g][2+h]);
                            mma16816(d, a1[f], b2r[g][0+h], b2r[g][2+h]);
                            mma16816(d, a2[f], b1r[g][0+h], b1r[g][2+h]);
                        }
            }
            BAR_ARRIVE(3 + bs);              // signal EMPTY[bs]
        }
    }

    __syncthreads();

    // ---- tile store epilogue (consumer warps hold acc) ----
    float* __restrict__ Sb = g_S + (size_t)b * NN * NN;
    const int r0 = lane >> 2;
    const int c0 = (lane & 3) * 2;
    const int wm = wid >> 2;
    const int wn = wid & 3;

    if (wid < 8) {
        #pragma unroll
        for (int f = 0; f < 4; f++) {
            const int gr = rbase + wm * 64 + f * 16 + r0;
            #pragma unroll
            for (int n = 0; n < 4; n++) {
                const int gc = cbase + wn * 32 + n * 8 + c0;
                float* d = acc[f][n];
                *(float2*)&Sb[(size_t)gr * NN + gc]       = make_float2(d[0], d[1]);
                *(float2*)&Sb[(size_t)(gr + 8) * NN + gc] = make_float2(d[2], d[3]);
            }
        }
    }

    if (jt > it) {
        float* st = (float*)smem;            // 128 x 129 floats
        if (wid < 8) {
            #pragma unroll
            for (int f = 0; f < 4; f++) {
                const int sr = wm * 64 + f * 16 + r0;
                #pragma unroll
                for (int n = 0; n < 4; n++) {
                    const int sc = wn * 32 + n * 8 + c0;
                    float* d = acc[f][n];
                    st[(size_t)sr * 129 + sc]           = d[0];
                    st[(size_t)sr * 129 + sc + 1]       = d[1];
                    st[(size_t)(sr + 8) * 129 + sc]     = d[2];
                    st[(size_t)(sr + 8) * 129 + sc + 1] = d[3];
                }
            }
        }
        __syncthreads();
        if (tid < 256) {
            const int mr = tid >> 1;
            const int hh = tid & 1;
            float* dst = Sb + (size_t)(cbase + mr) * NN + rbase + hh * 64;
            #pragma unroll
            for (int i = 0; i < 16; i++) {
                float4 v;
                v.x = st[(size_t)(hh * 64 + i * 4 + 0) * 129 + mr];
                v.y = st[(size_t)(hh * 64 + i * 4 + 1) * 129 + mr];
                v.z = st[(size_t)(hh * 64 + i * 4 + 2) * 129 + mr];
                v.w = st[(size_t)(hh * 64 + i * 4 + 3) * 129 + mr];
                *(float4*)(dst + i * 4) = v;
            }
        }
    }

    // ---- batch arrival: last CTA of this batch runs topk+normalize ----
    __syncthreads();
    __shared__ int s_last;
    if (tid == 0) {
        __threadfence();                              // release S writes
        unsigned int old = atomicAdd(&g_done[b], 1u);
        s_last = ((old % 10u) == 9u) ? 1 : 0;         // +10 per launch -> replay-safe
    }
    __syncthreads();
    if (!s_last) return;
    __threadfence();                                  // acquire other CTAs' S writes

    // ===================== fused batch epilogue =====================
    // smem reuse: masks[512][16] (32 KB) + rdeg[512] (2 KB)
    uint32_t* msk  = (uint32_t*)smem;                 // 512*16 words
    float*    rdg  = (float*)(smem + NN * 16 * 4);    // 512 floats

    // ---- phase 1: per-row top-32 threshold (one warp per row, 12 warps) ----
    #pragma unroll 1
    for (int r = wid; r < NN; r += 12) {
        const float* __restrict__ Sr = Sb + (size_t)r * NN;
        uint32_t u[16];
        const float4* S4 = (const float4*)Sr;
        #pragma unroll
        for (int j = 0; j < 4; j++) {
            float4 t = S4[lane + 32 * j];
            float f[4] = {t.x, t.y, t.z, t.w};
            #pragma unroll
            for (int q = 0; q < 4; q++) {
                uint32_t s = __float_as_uint(f[q]);
                u[4*j+q] = (s & 0x80000000u) ? ~s : (s | 0x80000000u);
            }
        }

        uint32_t s0 = 0, s1 = 0, s2 = 0, s3 = 0;
        #pragma unroll
        for (int j = 0; j < 16; j++) {
            uint32_t v = u[j], t;
            t = max(s0, v); v = min(s0, v); s0 = t;
            t = max(s1, v); v = min(s1, v); s1 = t;
            t = max(s2, v); v = min(s2, v); s2 = t;
            s3 = max(s3, v);
        }

        const uint32_t t0   = __reduce_min_sync(0xffffffffu, s0);
        const uint32_t tmax = __reduce_max_sync(0xffffffffu, s0);
        const uint32_t t2 = __reduce_max_sync(0xffffffffu, (s0 == tmax) ? s1 : s0);

        uint32_t thr;
        if (t0 >= t2) {
            thr = t0;
        } else {
            const int b0 = 31 - __clz(t0 ^ t2);
            const uint32_t low = (uint32_t)(((uint64_t)2 << b0) - 1u);
            thr = t0 & ~low;
            #pragma unroll 1
            for (int bit = b0; bit >= 0; bit--) {
                const uint32_t test = thr | (1u << bit);
                int c = (int)(s0 >= test) + (int)(s1 >= test)
                      + (int)(s2 >= test) + (int)(s3 >= test);
                if (c == 4) {
                    int cf = 0;
                    #pragma unroll
                    for (int j = 0; j < 16; j++) cf += (u[j] >= test);
                    c = cf;
                }
                c = __reduce_add_sync(0xffffffffu, c);
                if (c == 32) {
                    uint32_t lmin = 0xffffffffu;
                    #pragma unroll
                    for (int j = 0; j < 16; j++)
                        lmin = min(lmin, (u[j] >= test) ? u[j] : 0xffffffffu);
                    thr = __reduce_min_sync(0xffffffffu, lmin);
                    break;
                }
                if (c > 32) thr = test;
            }
        }

        int cnt = 0;
        #pragma unroll
        for (int j = 0; j < 16; j++) {
            uint32_t mm = __ballot_sync(0xffffffffu, u[j] >= thr);
            if (lane == j) { /* placeholder to keep mm live */ }
            cnt += __popc(mm);
            if (lane == 0) msk[r * 16 + j] = mm;
        }
        if (lane == 0) rdg[r] = rsqrtf((float)cnt);
    }
    __syncthreads();

    // ---- phase 2: normalize this batch (write-bound) ----
    float* __restrict__ outb = out + (size_t)b * NN * NN;
    #pragma unroll 1
    for (int idx = tid; idx < NN * (NN / 4); idx += NTHR) {
        const int f = idx & 127;
        const int r = idx >> 7;
        const int j = f >> 5;
        const int ln = f & 31;

        const uint4 mw = *(const uint4*)(msk + r * 16 + 4 * j);
        const float ri = rdg[r];
        const float* rj = rdg + f * 4;

        float4 o;
        o.x = ((mw.x >> ln) & 1u) ? ri * rj[0] : 0.0f;
        o.y = ((mw.y >> ln) & 1u) ? ri * rj[1] : 0.0f;
        o.z = ((mw.z >> ln) & 1u) ? ri * rj[2] : 0.0f;
        o.w = ((mw.w >> ln) & 1u) ? ri * rj[3] : 0.0f;
        ((float4*)outb)[idx] = o;
    }
}

// ---------------------------------------------------------------------------
extern "C" void kernel_launch(void* const* d_in, const int* in_sizes, int n_in,
                              void* d_out, int out_size)
{
    const float* x = (const float*)d_in[0];
    float* out = (float*)d_out;

    cudaFuncSetAttribute(gemm_fused_kernel,
                         cudaFuncAttributeMaxDynamicSharedMemorySize, SMEM_TOTAL);

    dim3 gGemm(10, BB);
    gemm_fused_kernel<<<gGemm, NTHR, SMEM_TOTAL>>>(x, out);
}